// round 7
// baseline (speedup 1.0000x reference)
#include <cuda_runtime.h>
#include <cuda_bf16.h>
#include <cstdint>

#define MAXN 100000
#define MAXE 1600000
#define HIDD 128
#define MAXG 512
#define BN_EPS 1e-5f

// ---------------- scratch (static device globals; no allocations) ------------
__device__ float g_h  [(size_t)MAXN * HIDD];
__device__ float g_m  [(size_t)MAXN * HIDD];
__device__ float g_p  [(size_t)MAXN * HIDD];
__device__ float g_pool[(size_t)MAXG * 3 * HIDD];
__device__ float g_cnt [MAXG];
__device__ float g_stats[2 * HIDD];
__device__ float g_scale2[3 * HIDD];
__device__ float g_shift2[3 * HIDD];
__device__ float g_emb [100 * HIDD];
// packed weights: [6 weights][hi/lo][64*136 words], smem-tile layout incl. pad
#define WS2 136
#define W_PLANE (64 * WS2)
__device__ uint32_t g_wpack[6][2][W_PLANE];
// CSR scratch
__device__ int g_deg [MAXN];
__device__ int g_off [MAXN];
__device__ int g_cur [MAXN];
__device__ int g_bsum[256];
__device__ int g_csr [MAXE];

// smem tile (words): Ahi[64][68], Alo[64][68], Whi[64][136], Wlo[64][136]
#define AS2 68
#define A_PLANE (64 * AS2)
#define SMEM_BYTES ((2 * A_PLANE + 2 * W_PLANE) * 4)   // 104448

// pair two consecutive-k values into one b16x2 word (low = even k)
__device__ __forceinline__ uint32_t hi_pair(float a, float b)
{
    return (__float_as_uint(a) >> 16) | (__float_as_uint(b) & 0xFFFF0000u);
}
__device__ __forceinline__ uint32_t lo_pair(float a, float b)
{
    float ra = a - __uint_as_float(__float_as_uint(a) & 0xFFFF0000u);
    float rb = b - __uint_as_float(__float_as_uint(b) & 0xFFFF0000u);
    uint32_t la = (uint32_t)__bfloat16_as_ushort(__float2bfloat16(ra));
    uint32_t lb = (uint32_t)__bfloat16_as_ushort(__float2bfloat16(rb));
    return la | (lb << 16);
}

__device__ __forceinline__ void mma_bf16(float c[4], const uint32_t a[4], const uint32_t b[2])
{
    asm volatile(
        "mma.sync.aligned.m16n8k16.row.col.f32.bf16.bf16.f32 "
        "{%0,%1,%2,%3}, {%4,%5,%6,%7}, {%8,%9}, {%0,%1,%2,%3};"
        : "+f"(c[0]), "+f"(c[1]), "+f"(c[2]), "+f"(c[3])
        : "r"(a[0]), "r"(a[1]), "r"(a[2]), "r"(a[3]), "r"(b[0]), "r"(b[1]));
}

// ---------------- bf16x3 tensor-core GEMM: out = f(A)[n,128] @ Wpack[widx] ---
// 64-row tiles, 2 CTAs/SM. f(A): optional BN affine. Optional +bias, +embsum[z],
// +relu, +BN-stats, +raw pooled-sum accumulation (linear-pool trick).
__global__ void __launch_bounds__(256, 2)
gemm_mma(const float* __restrict__ A, int widx,
         const float* __restrict__ bias, const int* __restrict__ z,
         const float* __restrict__ bnsc, const float* __restrict__ bnsh,
         float* __restrict__ out, int n, int do_relu, int do_stats, int do_emb,
         const int* __restrict__ batch, float* __restrict__ pool, int loff, int do_pool)
{
    extern __shared__ uint32_t sh[];
    uint32_t* Ahi = sh;
    uint32_t* Alo = sh + A_PLANE;
    uint32_t* Whi = sh + 2 * A_PLANE;
    uint32_t* Wlo = sh + 2 * A_PLANE + W_PLANE;
    const int tid  = threadIdx.x;            // 256
    const int row0 = blockIdx.x * 64;

    // stage W: straight uint4 copy of pre-packed planes (hi then lo, contiguous)
    {
        const uint4* src = (const uint4*)&g_wpack[widx][0][0];
        uint4* dst = (uint4*)Whi;
        for (int i = tid; i < (2 * W_PLANE) / 4; i += 256)
            dst[i] = src[i];
    }
    // stage A: pack consecutive k pairs, optional BN affine
    for (int i = tid; i < 2048; i += 256) {
        int r  = i >> 5;                 // 0..63
        int c4 = (i & 31) * 4;
        int row = row0 + r;
        float4 v = make_float4(0.f, 0.f, 0.f, 0.f);
        if (row < n) v = *(const float4*)&A[(size_t)row * 128 + c4];
        if (bnsc) {
            v.x = v.x * bnsc[c4 + 0] + bnsh[c4 + 0];
            v.y = v.y * bnsc[c4 + 1] + bnsh[c4 + 1];
            v.z = v.z * bnsc[c4 + 2] + bnsh[c4 + 2];
            v.w = v.w * bnsc[c4 + 3] + bnsh[c4 + 3];
        }
        uint2 hv, lv;
        hv.x = hi_pair(v.x, v.y); lv.x = lo_pair(v.x, v.y);
        hv.y = hi_pair(v.z, v.w); lv.y = lo_pair(v.z, v.w);
        *(uint2*)&Ahi[r * AS2 + (c4 >> 1)] = hv;
        *(uint2*)&Alo[r * AS2 + (c4 >> 1)] = lv;
    }
    __syncthreads();

    const int w    = tid >> 5;
    const int lane = tid & 31;
    const int wm0  = (w & 3) * 16;       // 4 warps in M (16 rows each)
    const int n0   = (w >> 2) * 64;      // 2 warps in N (64 cols each)
    const int g    = lane >> 2;
    const int t    = lane & 3;

    float c[8][4];
    #pragma unroll
    for (int nt = 0; nt < 8; nt++)
        #pragma unroll
        for (int j = 0; j < 4; j++) c[nt][j] = 0.f;

    #pragma unroll
    for (int kc = 0; kc < 8; kc++) {
        int kh16 = kc * 8;
        int base = (wm0 + g) * AS2 + kh16 + t;
        uint32_t ahi[4], alo[4];
        ahi[0] = Ahi[base];
        ahi[1] = Ahi[base + 8 * AS2];
        ahi[2] = Ahi[base + 4];
        ahi[3] = Ahi[base + 4 + 8 * AS2];
        alo[0] = Alo[base];
        alo[1] = Alo[base + 8 * AS2];
        alo[2] = Alo[base + 4];
        alo[3] = Alo[base + 4 + 8 * AS2];
        #pragma unroll
        for (int nt = 0; nt < 8; nt++) {
            int wb = (kh16 + t) * WS2 + n0 + nt * 8 + g;
            uint32_t bhi[2], blo[2];
            bhi[0] = Whi[wb];
            bhi[1] = Whi[wb + 4 * WS2];
            blo[0] = Wlo[wb];
            blo[1] = Wlo[wb + 4 * WS2];
            mma_bf16(c[nt], ahi, bhi);   // hi*hi
            mma_bf16(c[nt], ahi, blo);   // hi*lo
            mma_bf16(c[nt], alo, bhi);   // lo*hi
        }
    }

    // ---------------- epilogue ----------------
    float sst[16], qst[16];
    #pragma unroll
    for (int i = 0; i < 16; i++) { sst[i] = 0.f; qst[i] = 0.f; }

    #pragma unroll
    for (int rr = 0; rr < 2; rr++) {
        int row = row0 + wm0 + rr * 8 + g;
        bool valid = row < n;
        const float* er = nullptr;
        if (do_emb && valid) er = &g_emb[(size_t)z[row] * 128];
        float* prow = nullptr;
        if (do_pool && valid) prow = &pool[(size_t)batch[row] * 384 + loff];
        #pragma unroll
        for (int nt = 0; nt < 8; nt++) {
            int col0 = n0 + nt * 8 + 2 * t;
            float v0 = c[nt][rr * 2 + 0];
            float v1 = c[nt][rr * 2 + 1];
            if (bias) { v0 += bias[col0]; v1 += bias[col0 + 1]; }
            if (er)   { v0 += er[col0];   v1 += er[col0 + 1]; }
            if (do_relu) { v0 = fmaxf(v0, 0.f); v1 = fmaxf(v1, 0.f); }
            if (do_stats && valid) {
                sst[nt * 2 + 0] += v0; qst[nt * 2 + 0] += v0 * v0;
                sst[nt * 2 + 1] += v1; qst[nt * 2 + 1] += v1 * v1;
            }
            if (valid) {
                *(float2*)&out[(size_t)row * 128 + col0] = make_float2(v0, v1);
                if (prow)
                    asm volatile("red.global.add.v2.f32 [%0], {%1,%2};"
                                 :: "l"(prow + col0), "f"(v0), "f"(v1) : "memory");
            }
        }
    }

    if (do_stats) {
        #pragma unroll
        for (int i = 0; i < 16; i++) {
            #pragma unroll
            for (int msk = 4; msk < 32; msk <<= 1) {
                sst[i] += __shfl_xor_sync(0xffffffffu, sst[i], msk);
                qst[i] += __shfl_xor_sync(0xffffffffu, qst[i], msk);
            }
        }
        if (g == 0) {
            #pragma unroll
            for (int i = 0; i < 16; i++) {
                int col = n0 + (i >> 1) * 8 + 2 * t + (i & 1);
                atomicAdd(&g_stats[col], sst[i]);
                atomicAdd(&g_stats[128 + col], qst[i]);
            }
        }
    }
}

// ---------------- prep: embsum + pack all 6 weight matrices ------------------
// grid 98 x 256: blocks 0..49 = embsum (2 z-rows each); 50..97 = pack (8/weight)
__global__ void prep_k(const float* __restrict__ W0, const float* __restrict__ W1,
                       const float* __restrict__ W2, const float* __restrict__ W3,
                       const float* __restrict__ W4, const float* __restrict__ W5,
                       const float* __restrict__ W1_0full)
{
    int b = blockIdx.x;
    if (b < 50) {
        int zi = b * 2 + (threadIdx.x >> 7);
        int c  = threadIdx.x & 127;
        g_emb[zi * 128 + c] = W1_0full[zi * 128 + c] + W1_0full[(100 + zi) * 128 + c];
        return;
    }
    int widx = (b - 50) >> 3;
    int blk  = (b - 50) & 7;
    const float* W = W0;
    if (widx == 1) W = W1; else if (widx == 2) W = W2;
    else if (widx == 3) W = W3; else if (widx == 4) W = W4;
    else if (widx == 5) W = W5;
    int i  = blk * 256 + threadIdx.x;    // 0..2047
    int kh = i >> 5;
    int c4 = (i & 31) * 4;
    float4 r0 = *(const float4*)&W[(2 * kh)     * 128 + c4];
    float4 r1 = *(const float4*)&W[(2 * kh + 1) * 128 + c4];
    uint4 hv, lv;
    hv.x = hi_pair(r0.x, r1.x); lv.x = lo_pair(r0.x, r1.x);
    hv.y = hi_pair(r0.y, r1.y); lv.y = lo_pair(r0.y, r1.y);
    hv.z = hi_pair(r0.z, r1.z); lv.z = lo_pair(r0.z, r1.z);
    hv.w = hi_pair(r0.w, r1.w); lv.w = lo_pair(r0.w, r1.w);
    *(uint4*)&g_wpack[widx][0][kh * WS2 + c4] = hv;
    *(uint4*)&g_wpack[widx][1][kh * WS2 + c4] = lv;
}

// ---------------- CSR build --------------------------------------------------
__global__ void hist_k(const int* __restrict__ ei, int E)
{
    int e = blockIdx.x * blockDim.x + threadIdx.x;
    if (e < E) atomicAdd(&g_deg[ei[E + e]], 1);
}

__global__ void scan1_k(int n)
{
    __shared__ int s[1024];
    int t = threadIdx.x, i = blockIdx.x * 1024 + t;
    int v = (i < n) ? g_deg[i] : 0;
    s[t] = v;
    __syncthreads();
    #pragma unroll
    for (int d = 1; d < 1024; d <<= 1) {
        int x = (t >= d) ? s[t - d] : 0;
        __syncthreads();
        s[t] += x;
        __syncthreads();
    }
    if (i < n) g_off[i] = s[t] - v;
    if (t == 1023) g_bsum[blockIdx.x] = s[t];
}

__global__ void scan2_k(int nb)
{
    __shared__ int s[256];
    int t = threadIdx.x;
    int v = (t < nb) ? g_bsum[t] : 0;
    s[t] = v;
    __syncthreads();
    #pragma unroll
    for (int d = 1; d < 256; d <<= 1) {
        int x = (t >= d) ? s[t - d] : 0;
        __syncthreads();
        s[t] += x;
        __syncthreads();
    }
    if (t < nb) g_bsum[t] = s[t] - v;
}

__global__ void scan3_k(int n)
{
    int i = blockIdx.x * blockDim.x + threadIdx.x;
    if (i < n) g_off[i] += g_bsum[i >> 10];
}

__global__ void scatter_k(const int* __restrict__ ei, int E)
{
    int e = blockIdx.x * blockDim.x + threadIdx.x;
    if (e >= E) return;
    int dst = ei[E + e];
    int pos = g_off[dst] + atomicAdd(&g_cur[dst], 1);
    g_csr[pos] = ei[e];
}

// ---------------- fused aggregation: m = relu(p + sum_csr p[src] + b1) -------
__global__ void agg_fused(const float* __restrict__ p, const float* __restrict__ b,
                          float* __restrict__ out, int n)
{
    int w    = (blockIdx.x * blockDim.x + threadIdx.x) >> 5;
    int lane = threadIdx.x & 31;
    if (w >= n) return;
    int off = g_off[w], deg = g_deg[w];
    const float* pc = p + (size_t)lane * 4;
    float4 acc = *(const float4*)&pc[(size_t)w * 128];

    for (int base = 0; base < deg; base += 32) {
        int idx = 0;
        if (base + lane < deg) idx = g_csr[off + base + lane];
        int cnt = min(32, deg - base);
        int j = 0;
        for (; j + 4 <= cnt; j += 4) {
            int s0 = __shfl_sync(0xffffffffu, idx, j);
            int s1 = __shfl_sync(0xffffffffu, idx, j + 1);
            int s2 = __shfl_sync(0xffffffffu, idx, j + 2);
            int s3 = __shfl_sync(0xffffffffu, idx, j + 3);
            float4 v0 = *(const float4*)&pc[(size_t)s0 * 128];
            float4 v1 = *(const float4*)&pc[(size_t)s1 * 128];
            float4 v2 = *(const float4*)&pc[(size_t)s2 * 128];
            float4 v3 = *(const float4*)&pc[(size_t)s3 * 128];
            acc.x += v0.x + v1.x + v2.x + v3.x;
            acc.y += v0.y + v1.y + v2.y + v3.y;
            acc.z += v0.z + v1.z + v2.z + v3.z;
            acc.w += v0.w + v1.w + v2.w + v3.w;
        }
        for (; j < cnt; j++) {
            int s = __shfl_sync(0xffffffffu, idx, j);
            float4 v = *(const float4*)&pc[(size_t)s * 128];
            acc.x += v.x; acc.y += v.y; acc.z += v.z; acc.w += v.w;
        }
    }
    float4 bv = *(const float4*)&b[lane * 4];
    float4 o;
    o.x = fmaxf(acc.x + bv.x, 0.f);
    o.y = fmaxf(acc.y + bv.y, 0.f);
    o.z = fmaxf(acc.z + bv.z, 0.f);
    o.w = fmaxf(acc.w + bv.w, 0.f);
    *(float4*)&out[(size_t)w * 128 + lane * 4] = o;
}

// ---------------- per-graph node counts --------------------------------------
__global__ void count_k(const int* __restrict__ batch, float* __restrict__ cnt, int n)
{
    int i = blockIdx.x * blockDim.x + threadIdx.x;
    if (i < n) atomicAdd(&cnt[batch[i]], 1.0f);
}

// ---------------- BN coefficients from stats (per layer) ---------------------
__global__ void bn_coef(const float* __restrict__ gamma, const float* __restrict__ beta,
                        int n, int l)
{
    int c = threadIdx.x;
    float invn = 1.0f / (float)n;
    float mu   = g_stats[c] * invn;
    float var  = g_stats[128 + c] * invn - mu * mu;
    float rstd = rsqrtf(var + BN_EPS);
    float sc   = gamma[c] * rstd;
    g_scale2[l * 128 + c] = sc;
    g_shift2[l * 128 + c] = beta[c] - mu * sc;
}

// ---------------- final head (applies linear-pool BN correction) -------------
__global__ void final_mlp(const float* __restrict__ Wl1, const float* __restrict__ bl1,
                          const float* __restrict__ Wl2, const float* __restrict__ bl2,
                          float* __restrict__ out)
{
    int g = blockIdx.x, tid = threadIdx.x;
    __shared__ float pooled[384];
    float cntv = g_cnt[g];
    float ic   = 1.0f / fmaxf(cntv, 1.0f);
    float have = cntv * ic;
    for (int i = tid; i < 384; i += 128)
        pooled[i] = g_pool[(size_t)g * 384 + i] * g_scale2[i] * ic + g_shift2[i] * have;
    __syncthreads();
    float a = bl1[tid];
    #pragma unroll 4
    for (int k = 0; k < 384; k++)
        a = fmaf(pooled[k], Wl1[k * 128 + tid], a);
    float v = fmaxf(a, 0.f) * Wl2[tid];
    #pragma unroll
    for (int o = 16; o; o >>= 1) v += __shfl_xor_sync(0xffffffffu, v, o);
    __shared__ float ws[4];
    if ((tid & 31) == 0) ws[tid >> 5] = v;
    __syncthreads();
    if (tid == 0) out[g] = ws[0] + ws[1] + ws[2] + ws[3] + bl2[0];
}

// -----------------------------------------------------------------------------
extern "C" void kernel_launch(void* const* d_in, const int* in_sizes, int n_in,
                              void* d_out, int out_size)
{
    const float* x     = (const float*)d_in[0];
    const int*   z     = (const int*)  d_in[1];
    const int*   ei    = (const int*)  d_in[2];
    const int*   batch = (const int*)  d_in[3];
    const float *W1[3], *b1[3], *W2[3], *b2[3], *ga[3], *be[3];
    for (int l = 0; l < 3; l++) {
        W1[l] = (const float*)d_in[4 + 6 * l];
        b1[l] = (const float*)d_in[5 + 6 * l];
        W2[l] = (const float*)d_in[6 + 6 * l];
        b2[l] = (const float*)d_in[7 + 6 * l];
        ga[l] = (const float*)d_in[8 + 6 * l];
        be[l] = (const float*)d_in[9 + 6 * l];
    }
    const float* Wl1 = (const float*)d_in[22];
    const float* bl1 = (const float*)d_in[23];
    const float* Wl2 = (const float*)d_in[24];
    const float* bl2 = (const float*)d_in[25];
    float* out = (float*)d_out;

    int n = in_sizes[0] / 128;
    int E = in_sizes[2] / 2;
    int G = out_size;

    float *p_h, *p_m, *p_p, *p_pool, *p_cnt, *p_stats, *p_scale2, *p_shift2;
    int *p_deg, *p_cur;
    cudaGetSymbolAddress((void**)&p_h,      g_h);
    cudaGetSymbolAddress((void**)&p_m,      g_m);
    cudaGetSymbolAddress((void**)&p_p,      g_p);
    cudaGetSymbolAddress((void**)&p_pool,   g_pool);
    cudaGetSymbolAddress((void**)&p_cnt,    g_cnt);
    cudaGetSymbolAddress((void**)&p_stats,  g_stats);
    cudaGetSymbolAddress((void**)&p_scale2, g_scale2);
    cudaGetSymbolAddress((void**)&p_shift2, g_shift2);
    cudaGetSymbolAddress((void**)&p_deg,    g_deg);
    cudaGetSymbolAddress((void**)&p_cur,    g_cur);

    cudaFuncSetAttribute(gemm_mma, cudaFuncAttributeMaxDynamicSharedMemorySize, SMEM_BYTES);

    int    gb64  = (n + 63) / 64;
    size_t tot32 = (size_t)n * 32;
    int    nb32  = (int)((tot32 + 255) / 256);
    int    nb_scan = (n + 1023) / 1024;

    // ---- setup (same launch-prefix count: 4 memsets + 3 kernels, gemm is #8) --
    cudaMemsetAsync(p_pool, 0, (size_t)G * 384 * sizeof(float));   // 1
    cudaMemsetAsync(p_cnt,  0, (size_t)G * sizeof(float));         // 2
    cudaMemsetAsync(p_deg,  0, (size_t)n * sizeof(int));           // 3
    cudaMemsetAsync(p_cur,  0, (size_t)n * sizeof(int));           // 4
    count_k<<<(n + 255) / 256, 256>>>(batch, p_cnt, n);            // 5
    prep_k<<<98, 256>>>(W1[0] + 200 * 128, W2[0], W1[1], W2[1],    // 6
                        W1[2], W2[2], W1[0]);
    hist_k<<<(E + 255) / 256, 256>>>(ei, E);                       // 7

    // layer-0 GEMM1: p = x @ W1_0[200:] + embsum[z]                // 8
    gemm_mma<<<gb64, 256, SMEM_BYTES>>>(x, 0, nullptr, z,
                                        nullptr, nullptr, p_h, n, 0, 0, 1,
                                        nullptr, nullptr, 0, 0);

    scan1_k  <<<nb_scan, 1024>>>(n);
    scan2_k  <<<1, 256>>>(nb_scan);
    scan3_k  <<<(n + 255) / 256, 256>>>(n);
    scatter_k<<<(E + 255) / 256, 256>>>(ei, E);

    for (int l = 0; l < 3; l++) {
        if (l > 0)
            gemm_mma<<<gb64, 256, SMEM_BYTES>>>(p_p, 2 * l, nullptr, nullptr,
                                                p_scale2 + (l - 1) * 128,
                                                p_shift2 + (l - 1) * 128,
                                                p_h, n, 0, 0, 0,
                                                nullptr, nullptr, 0, 0);

        // m = relu(p + sum_{src->i} p[src] + b1)
        agg_fused<<<nb32, 256>>>(p_h, b1[l], p_m, n);

        // t = relu(m @ W2 + b2), fused BN-stats + raw pooled-sum accumulation
        cudaMemsetAsync(p_stats, 0, 256 * sizeof(float));
        gemm_mma<<<gb64, 256, SMEM_BYTES>>>(p_m, 2 * l + 1, b2[l], nullptr,
                                            nullptr, nullptr, p_p, n, 1, 1, 0,
                                            batch, p_pool, l * 128, 1);

        bn_coef<<<1, 128>>>(ga[l], be[l], n, l);
    }

    final_mlp<<<G, 128>>>(Wl1, bl1, Wl2, bl2, out);
}

// round 9
// speedup vs baseline: 1.0266x; 1.0266x over previous
#include <cuda_runtime.h>
#include <cuda_bf16.h>
#include <cstdint>

#define MAXN 100000
#define MAXE 1600000
#define HIDD 128
#define MAXG 512
#define BN_EPS 1e-5f

// ---------------- scratch (static device globals; no allocations) ------------
__device__ float g_h  [(size_t)MAXN * HIDD];
__device__ float g_m  [(size_t)MAXN * HIDD];
__device__ float g_p  [(size_t)MAXN * HIDD];
__device__ float g_pool[(size_t)MAXG * 3 * HIDD];
__device__ float g_cnt [MAXG];
__device__ float g_stats[2 * HIDD];
__device__ float g_scale2[3 * HIDD];
__device__ float g_shift2[3 * HIDD];
__device__ float g_emb [100 * HIDD];
// packed weights, fragment-pair layout: plane word idx = kc*1024 + col*8 + t*2 + p
// (word holds bf16x2 for k = 2*kh, 2*kh+1 where kh = kc*8 + t + 4p)
#define W_PLANE 8192
__device__ uint32_t g_wpack[6][2][W_PLANE];
// CSR scratch
__device__ int g_deg [MAXN];
__device__ int g_off [MAXN];
__device__ int g_cur [MAXN];
__device__ int g_bsum[256];
__device__ int g_csr [MAXE];

// smem: Ahi[64*72], Alo[64*72], Whi[8192], Wlo[8192]  (words)
#define A_STRIDE 72
#define A_PLANE (64 * A_STRIDE)
#define SMEM_BYTES ((2 * A_PLANE + 2 * W_PLANE) * 4)   // 102400

// pair two consecutive-k values into one b16x2 word (low = even k)
__device__ __forceinline__ uint32_t hi_pair(float a, float b)
{
    return (__float_as_uint(a) >> 16) | (__float_as_uint(b) & 0xFFFF0000u);
}
__device__ __forceinline__ uint32_t lo_pair(float a, float b)
{
    float ra = a - __uint_as_float(__float_as_uint(a) & 0xFFFF0000u);
    float rb = b - __uint_as_float(__float_as_uint(b) & 0xFFFF0000u);
    uint32_t la = (uint32_t)__bfloat16_as_ushort(__float2bfloat16(ra));
    uint32_t lb = (uint32_t)__bfloat16_as_ushort(__float2bfloat16(rb));
    return la | (lb << 16);
}

// position of kh-word within one A row segment / one W kc-col segment
__device__ __forceinline__ int kh_pos(int kh)
{
    return ((kh >> 3) << 3) * 0 + (kh & 3) * 2 + ((kh >> 2) & 1);   // within kc: t*2+p
}

__device__ __forceinline__ void mma_bf16(float c[4], const uint32_t a[4], const uint32_t b[2])
{
    asm volatile(
        "mma.sync.aligned.m16n8k16.row.col.f32.bf16.bf16.f32 "
        "{%0,%1,%2,%3}, {%4,%5,%6,%7}, {%8,%9}, {%0,%1,%2,%3};"
        : "+f"(c[0]), "+f"(c[1]), "+f"(c[2]), "+f"(c[3])
        : "r"(a[0]), "r"(a[1]), "r"(a[2]), "r"(a[3]), "r"(b[0]), "r"(b[1]));
}

// ---------------- bf16x3 tensor-core GEMM: out = f(A)[n,128] @ Wpack[widx] ---
__global__ void __launch_bounds__(256, 2)
gemm_mma(const float* __restrict__ A, int widx,
         const float* __restrict__ bias, const int* __restrict__ z,
         const float* __restrict__ bnsc, const float* __restrict__ bnsh,
         float* __restrict__ out, int n, int do_relu, int do_stats, int do_emb,
         const int* __restrict__ batch, float* __restrict__ pool, int loff, int do_pool)
{
    extern __shared__ uint32_t sh[];
    uint32_t* Ahi = sh;
    uint32_t* Alo = sh + A_PLANE;
    uint32_t* Whi = sh + 2 * A_PLANE;
    uint32_t* Wlo = sh + 2 * A_PLANE + W_PLANE;
    const int tid  = threadIdx.x;            // 256
    const int row0 = blockIdx.x * 64;

    // stage W: straight uint4 copy (hi plane then lo plane, contiguous)
    {
        const uint4* src = (const uint4*)&g_wpack[widx][0][0];
        uint4* dst = (uint4*)Whi;
        for (int i = tid; i < (2 * W_PLANE) / 4; i += 256)
            dst[i] = src[i];
    }
    // stage A into fragment-pair layout, optional BN affine
    for (int i = tid; i < 2048; i += 256) {
        int r  = i >> 5;                 // 0..63
        int c4 = (i & 31) * 4;           // k = c4..c4+3
        int row = row0 + r;
        float4 v = make_float4(0.f, 0.f, 0.f, 0.f);
        if (row < n) v = *(const float4*)&A[(size_t)row * 128 + c4];
        if (bnsc) {
            v.x = v.x * bnsc[c4 + 0] + bnsh[c4 + 0];
            v.y = v.y * bnsc[c4 + 1] + bnsh[c4 + 1];
            v.z = v.z * bnsc[c4 + 2] + bnsh[c4 + 2];
            v.w = v.w * bnsc[c4 + 3] + bnsh[c4 + 3];
        }
        int kh0 = (i & 31) * 2, kh1 = kh0 + 1;
        int p0 = r * A_STRIDE + ((kh0 >> 3) << 3) + (kh0 & 3) * 2 + ((kh0 >> 2) & 1);
        int p1 = r * A_STRIDE + ((kh1 >> 3) << 3) + (kh1 & 3) * 2 + ((kh1 >> 2) & 1);
        Ahi[p0] = hi_pair(v.x, v.y);
        Ahi[p1] = hi_pair(v.z, v.w);
        Alo[p0] = lo_pair(v.x, v.y);
        Alo[p1] = lo_pair(v.z, v.w);
    }
    __syncthreads();

    const int w    = tid >> 5;
    const int lane = tid & 31;
    const int wm0  = (w & 3) * 16;       // 4 warps in M (16 rows each)
    const int n0   = (w >> 2) * 64;      // 2 warps in N (64 cols each)
    const int g    = lane >> 2;
    const int t    = lane & 3;

    float c[8][4];
    #pragma unroll
    for (int nt = 0; nt < 8; nt++)
        #pragma unroll
        for (int j = 0; j < 4; j++) c[nt][j] = 0.f;

    const int abase = (wm0 + g) * A_STRIDE + 2 * t;
    const int wbase = (n0 + g) * 8 + 2 * t;

    #pragma unroll
    for (int kc = 0; kc < 8; kc++) {
        int ab = abase + kc * 8;
        uint2 Ah0 = *(uint2*)&Ahi[ab];
        uint2 Ah1 = *(uint2*)&Ahi[ab + 8 * A_STRIDE];
        uint2 Al0 = *(uint2*)&Alo[ab];
        uint2 Al1 = *(uint2*)&Alo[ab + 8 * A_STRIDE];
        uint32_t ahi[4] = {Ah0.x, Ah1.x, Ah0.y, Ah1.y};
        uint32_t alo[4] = {Al0.x, Al1.x, Al0.y, Al1.y};
        int wb = wbase + kc * 1024;
        #pragma unroll
        for (int nt = 0; nt < 8; nt++) {
            uint2 Bh = *(uint2*)&Whi[wb + nt * 64];
            uint2 Bl = *(uint2*)&Wlo[wb + nt * 64];
            uint32_t bhi[2] = {Bh.x, Bh.y};
            uint32_t blo[2] = {Bl.x, Bl.y};
            mma_bf16(c[nt], ahi, bhi);   // hi*hi
            mma_bf16(c[nt], ahi, blo);   // hi*lo
            mma_bf16(c[nt], alo, bhi);   // lo*hi
        }
    }

    // ---------------- epilogue ----------------
    float sst[16], qst[16];
    #pragma unroll
    for (int i = 0; i < 16; i++) { sst[i] = 0.f; qst[i] = 0.f; }

    #pragma unroll
    for (int rr = 0; rr < 2; rr++) {
        int row = row0 + wm0 + rr * 8 + g;
        bool valid = row < n;
        const float* er = nullptr;
        if (do_emb && valid) er = &g_emb[(size_t)z[row] * 128];
        float* prow = nullptr;
        if (do_pool && valid) prow = &pool[(size_t)batch[row] * 384 + loff];
        #pragma unroll
        for (int nt = 0; nt < 8; nt++) {
            int col0 = n0 + nt * 8 + 2 * t;
            float v0 = c[nt][rr * 2 + 0];
            float v1 = c[nt][rr * 2 + 1];
            if (bias) { v0 += bias[col0]; v1 += bias[col0 + 1]; }
            if (er)   { v0 += er[col0];   v1 += er[col0 + 1]; }
            if (do_relu) { v0 = fmaxf(v0, 0.f); v1 = fmaxf(v1, 0.f); }
            if (do_stats && valid) {
                sst[nt * 2 + 0] += v0; qst[nt * 2 + 0] += v0 * v0;
                sst[nt * 2 + 1] += v1; qst[nt * 2 + 1] += v1 * v1;
            }
            if (valid) {
                *(float2*)&out[(size_t)row * 128 + col0] = make_float2(v0, v1);
                if (prow)
                    asm volatile("red.global.add.v2.f32 [%0], {%1,%2};"
                                 :: "l"(prow + col0), "f"(v0), "f"(v1) : "memory");
            }
        }
    }

    if (do_stats) {
        #pragma unroll
        for (int i = 0; i < 16; i++) {
            #pragma unroll
            for (int msk = 4; msk < 32; msk <<= 1) {
                sst[i] += __shfl_xor_sync(0xffffffffu, sst[i], msk);
                qst[i] += __shfl_xor_sync(0xffffffffu, qst[i], msk);
            }
        }
        if (g == 0) {
            #pragma unroll
            for (int i = 0; i < 16; i++) {
                int col = n0 + (i >> 1) * 8 + 2 * t + (i & 1);
                atomicAdd(&g_stats[col], sst[i]);
                atomicAdd(&g_stats[128 + col], qst[i]);
            }
        }
    }
}

// ---------------- prep: embsum + pack all 6 weight matrices ------------------
// blocks 0..49 = embsum; 50..97 = pack (8 blocks per weight)
__global__ void prep_k(const float* __restrict__ W0, const float* __restrict__ W1,
                       const float* __restrict__ W2, const float* __restrict__ W3,
                       const float* __restrict__ W4, const float* __restrict__ W5,
                       const float* __restrict__ W1_0full)
{
    int b = blockIdx.x;
    if (b < 50) {
        int zi = b * 2 + (threadIdx.x >> 7);
        int c  = threadIdx.x & 127;
        g_emb[zi * 128 + c] = W1_0full[zi * 128 + c] + W1_0full[(100 + zi) * 128 + c];
        return;
    }
    int widx = (b - 50) >> 3;
    int blk  = (b - 50) & 7;
    const float* W = W0;
    if (widx == 1) W = W1; else if (widx == 2) W = W2;
    else if (widx == 3) W = W3; else if (widx == 4) W = W4;
    else if (widx == 5) W = W5;
    int i  = blk * 256 + threadIdx.x;    // 0..2047
    int kh = i >> 5;
    int c4 = (i & 31) * 4;
    float4 r0 = *(const float4*)&W[(2 * kh)     * 128 + c4];
    float4 r1 = *(const float4*)&W[(2 * kh + 1) * 128 + c4];
    int kc = kh >> 3, t = kh & 3, p = (kh >> 2) & 1;
    int base = kc * 1024 + t * 2 + p;
    float h[4] = {r0.x, r0.y, r0.z, r0.w};
    float l[4] = {r1.x, r1.y, r1.z, r1.w};
    #pragma unroll
    for (int j = 0; j < 4; j++) {
        int pos = base + (c4 + j) * 8;
        g_wpack[widx][0][pos] = hi_pair(h[j], l[j]);
        g_wpack[widx][1][pos] = lo_pair(h[j], l[j]);
    }
}

// ---------------- CSR build --------------------------------------------------
__global__ void hist_k(const int* __restrict__ ei, int E)
{
    int e = blockIdx.x * blockDim.x + threadIdx.x;
    if (e < E) atomicAdd(&g_deg[ei[E + e]], 1);
}

__global__ void scan1_k(int n)
{
    __shared__ int s[1024];
    int t = threadIdx.x, i = blockIdx.x * 1024 + t;
    int v = (i < n) ? g_deg[i] : 0;
    s[t] = v;
    __syncthreads();
    #pragma unroll
    for (int d = 1; d < 1024; d <<= 1) {
        int x = (t >= d) ? s[t - d] : 0;
        __syncthreads();
        s[t] += x;
        __syncthreads();
    }
    if (i < n) g_off[i] = s[t] - v;
    if (t == 1023) g_bsum[blockIdx.x] = s[t];
}

__global__ void scan2_k(int nb)
{
    __shared__ int s[256];
    int t = threadIdx.x;
    int v = (t < nb) ? g_bsum[t] : 0;
    s[t] = v;
    __syncthreads();
    #pragma unroll
    for (int d = 1; d < 256; d <<= 1) {
        int x = (t >= d) ? s[t - d] : 0;
        __syncthreads();
        s[t] += x;
        __syncthreads();
    }
    if (t < nb) g_bsum[t] = s[t] - v;
}

__global__ void scan3_k(int n)
{
    int i = blockIdx.x * blockDim.x + threadIdx.x;
    if (i < n) g_off[i] += g_bsum[i >> 10];
}

__global__ void scatter_k(const int* __restrict__ ei, int E)
{
    int e = blockIdx.x * blockDim.x + threadIdx.x;
    if (e >= E) return;
    int dst = ei[E + e];
    int pos = g_off[dst] + atomicAdd(&g_cur[dst], 1);
    g_csr[pos] = ei[e];
}

// ---------------- fused aggregation: m = relu(p + sum_csr p[src] + b1) -------
__global__ void agg_fused(const float* __restrict__ p, const float* __restrict__ b,
                          float* __restrict__ out, int n)
{
    int w    = (blockIdx.x * blockDim.x + threadIdx.x) >> 5;
    int lane = threadIdx.x & 31;
    if (w >= n) return;
    int off = g_off[w], deg = g_deg[w];
    const float* pc = p + (size_t)lane * 4;
    float4 acc = *(const float4*)&pc[(size_t)w * 128];

    for (int base = 0; base < deg; base += 32) {
        int idx = 0;
        if (base + lane < deg) idx = g_csr[off + base + lane];
        int cnt = min(32, deg - base);
        int j = 0;
        for (; j + 4 <= cnt; j += 4) {
            int s0 = __shfl_sync(0xffffffffu, idx, j);
            int s1 = __shfl_sync(0xffffffffu, idx, j + 1);
            int s2 = __shfl_sync(0xffffffffu, idx, j + 2);
            int s3 = __shfl_sync(0xffffffffu, idx, j + 3);
            float4 v0 = *(const float4*)&pc[(size_t)s0 * 128];
            float4 v1 = *(const float4*)&pc[(size_t)s1 * 128];
            float4 v2 = *(const float4*)&pc[(size_t)s2 * 128];
            float4 v3 = *(const float4*)&pc[(size_t)s3 * 128];
            acc.x += v0.x + v1.x + v2.x + v3.x;
            acc.y += v0.y + v1.y + v2.y + v3.y;
            acc.z += v0.z + v1.z + v2.z + v3.z;
            acc.w += v0.w + v1.w + v2.w + v3.w;
        }
        for (; j < cnt; j++) {
            int s = __shfl_sync(0xffffffffu, idx, j);
            float4 v = *(const float4*)&pc[(size_t)s * 128];
            acc.x += v.x; acc.y += v.y; acc.z += v.z; acc.w += v.w;
        }
    }
    float4 bv = *(const float4*)&b[lane * 4];
    float4 o;
    o.x = fmaxf(acc.x + bv.x, 0.f);
    o.y = fmaxf(acc.y + bv.y, 0.f);
    o.z = fmaxf(acc.z + bv.z, 0.f);
    o.w = fmaxf(acc.w + bv.w, 0.f);
    *(float4*)&out[(size_t)w * 128 + lane * 4] = o;
}

// ---------------- per-graph node counts --------------------------------------
__global__ void count_k(const int* __restrict__ batch, float* __restrict__ cnt, int n)
{
    int i = blockIdx.x * blockDim.x + threadIdx.x;
    if (i < n) atomicAdd(&cnt[batch[i]], 1.0f);
}

// ---------------- BN coefficients from stats (per layer) ---------------------
__global__ void bn_coef(const float* __restrict__ gamma, const float* __restrict__ beta,
                        int n, int l)
{
    int c = threadIdx.x;
    float invn = 1.0f / (float)n;
    float mu   = g_stats[c] * invn;
    float var  = g_stats[128 + c] * invn - mu * mu;
    float rstd = rsqrtf(var + BN_EPS);
    float sc   = gamma[c] * rstd;
    g_scale2[l * 128 + c] = sc;
    g_shift2[l * 128 + c] = beta[c] - mu * sc;
}

// ---------------- final head (applies linear-pool BN correction) -------------
__global__ void final_mlp(const float* __restrict__ Wl1, const float* __restrict__ bl1,
                          const float* __restrict__ Wl2, const float* __restrict__ bl2,
                          float* __restrict__ out)
{
    int g = blockIdx.x, tid = threadIdx.x;
    __shared__ float pooled[384];
    float cntv = g_cnt[g];
    float ic   = 1.0f / fmaxf(cntv, 1.0f);
    float have = cntv * ic;
    for (int i = tid; i < 384; i += 128)
        pooled[i] = g_pool[(size_t)g * 384 + i] * g_scale2[i] * ic + g_shift2[i] * have;
    __syncthreads();
    float a = bl1[tid];
    #pragma unroll 4
    for (int k = 0; k < 384; k++)
        a = fmaf(pooled[k], Wl1[k * 128 + tid], a);
    float v = fmaxf(a, 0.f) * Wl2[tid];
    #pragma unroll
    for (int o = 16; o; o >>= 1) v += __shfl_xor_sync(0xffffffffu, v, o);
    __shared__ float ws[4];
    if ((tid & 31) == 0) ws[tid >> 5] = v;
    __syncthreads();
    if (tid == 0) out[g] = ws[0] + ws[1] + ws[2] + ws[3] + bl2[0];
}

// -----------------------------------------------------------------------------
extern "C" void kernel_launch(void* const* d_in, const int* in_sizes, int n_in,
                              void* d_out, int out_size)
{
    const float* x     = (const float*)d_in[0];
    const int*   z     = (const int*)  d_in[1];
    const int*   ei    = (const int*)  d_in[2];
    const int*   batch = (const int*)  d_in[3];
    const float *W1[3], *b1[3], *W2[3], *b2[3], *ga[3], *be[3];
    for (int l = 0; l < 3; l++) {
        W1[l] = (const float*)d_in[4 + 6 * l];
        b1[l] = (const float*)d_in[5 + 6 * l];
        W2[l] = (const float*)d_in[6 + 6 * l];
        b2[l] = (const float*)d_in[7 + 6 * l];
        ga[l] = (const float*)d_in[8 + 6 * l];
        be[l] = (const float*)d_in[9 + 6 * l];
    }
    const float* Wl1 = (const float*)d_in[22];
    const float* bl1 = (const float*)d_in[23];
    const float* Wl2 = (const float*)d_in[24];
    const float* bl2 = (const float*)d_in[25];
    float* out = (float*)d_out;

    int n = in_sizes[0] / 128;
    int E = in_sizes[2] / 2;
    int G = out_size;

    float *p_h, *p_m, *p_p, *p_pool, *p_cnt, *p_stats, *p_scale2, *p_shift2;
    int *p_deg, *p_cur;
    cudaGetSymbolAddress((void**)&p_h,      g_h);
    cudaGetSymbolAddress((void**)&p_m,      g_m);
    cudaGetSymbolAddress((void**)&p_p,      g_p);
    cudaGetSymbolAddress((void**)&p_pool,   g_pool);
    cudaGetSymbolAddress((void**)&p_cnt,    g_cnt);
    cudaGetSymbolAddress((void**)&p_stats,  g_stats);
    cudaGetSymbolAddress((void**)&p_scale2, g_scale2);
    cudaGetSymbolAddress((void**)&p_shift2, g_shift2);
    cudaGetSymbolAddress((void**)&p_deg,    g_deg);
    cudaGetSymbolAddress((void**)&p_cur,    g_cur);

    cudaFuncSetAttribute(gemm_mma, cudaFuncAttributeMaxDynamicSharedMemorySize, SMEM_BYTES);

    int    gb64  = (n + 63) / 64;
    size_t tot32 = (size_t)n * 32;
    int    nb32  = (int)((tot32 + 255) / 256);
    int    nb_scan = (n + 1023) / 1024;

    // ---- setup (same launch-prefix count: gemm is launch #8) -----------------
    cudaMemsetAsync(p_pool, 0, (size_t)G * 384 * sizeof(float));   // 1
    cudaMemsetAsync(p_cnt,  0, (size_t)G * sizeof(float));         // 2
    cudaMemsetAsync(p_deg,  0, (size_t)n * sizeof(int));           // 3
    cudaMemsetAsync(p_cur,  0, (size_t)n * sizeof(int));           // 4
    count_k<<<(n + 255) / 256, 256>>>(batch, p_cnt, n);            // 5
    prep_k<<<98, 256>>>(W1[0] + 200 * 128, W2[0], W1[1], W2[1],    // 6
                        W1[2], W2[2], W1[0]);
    hist_k<<<(E + 255) / 256, 256>>>(ei, E);                       // 7

    // layer-0 GEMM1: p = x @ W1_0[200:] + embsum[z]                // 8
    gemm_mma<<<gb64, 256, SMEM_BYTES>>>(x, 0, nullptr, z,
                                        nullptr, nullptr, p_h, n, 0, 0, 1,
                                        nullptr, nullptr, 0, 0);

    scan1_k  <<<nb_scan, 1024>>>(n);
    scan2_k  <<<1, 256>>>(nb_scan);
    scan3_k  <<<(n + 255) / 256, 256>>>(n);
    scatter_k<<<(E + 255) / 256, 256>>>(ei, E);

    for (int l = 0; l < 3; l++) {
        if (l > 0)
            gemm_mma<<<gb64, 256, SMEM_BYTES>>>(p_p, 2 * l, nullptr, nullptr,
                                                p_scale2 + (l - 1) * 128,
                                                p_shift2 + (l - 1) * 128,
                                                p_h, n, 0, 0, 0,
                                                nullptr, nullptr, 0, 0);

        // m = relu(p + sum_{src->i} p[src] + b1)
        agg_fused<<<nb32, 256>>>(p_h, b1[l], p_m, n);

        // t = relu(m @ W2 + b2), fused BN-stats + raw pooled-sum accumulation
        cudaMemsetAsync(p_stats, 0, 256 * sizeof(float));
        gemm_mma<<<gb64, 256, SMEM_BYTES>>>(p_m, 2 * l + 1, b2[l], nullptr,
                                            nullptr, nullptr, p_p, n, 1, 1, 0,
                                            batch, p_pool, l * 128, 1);

        bn_coef<<<1, 128>>>(ga[l], be[l], n, l);
    }

    final_mlp<<<G, 128>>>(Wl1, bl1, Wl2, bl2, out);
}